// round 13
// baseline (speedup 1.0000x reference)
#include <cuda_runtime.h>
#include <cuda_bf16.h>
#include <stdint.h>
#include <float.h>

// Problem constants
#define NG    128
#define NPG   64
#define EPG   1024
#define ETOT  131072
#define HD    128
#define FD    384
#define KSEL  32
#define DOUT  10
#define NT    384      // 12 warps: 8 MMA + 4 stagers

typedef uint32_t u32;

// ---- smem byte layout (bf16 buffers, row stride 144B) ----
#define SB2     144
#define FT_LO   18432          // lo half within a feature buffer (128 rows x 144B)
#define OFF_FT0 0              // h1 hi+lo  36864B
#define OFF_FT1 36864          // h2
#define OFF_FT2 73728          // x then h3
#define OFF_ABF 110592         // A_adj bf16 hi (64x144); lo +9216
#define ABF_LO  9216
#define OFF_WT0 129024         // W^T chunk buf0 (hi 18432 + lo 18432)
#define OFF_WT1 165888         // W^T chunk buf1
#define WT_LO   18432
// fp32 region (float indices into sm[])
#define FI_AF    50688         // 64 x 65
#define SAF      65
#define FI_WAS   54848         // 384
#define FI_BS    55232         // 384 (all 3 layer biases)
#define FI_RD    55616         // 768
#define FI_PSUM  56384         // 384
#define FI_T1    56768         // 128
#define FI_T2    56896         // 64
#define FI_SDOT  56960         // 64
#define FI_SCORE 57024         // 64
#define FI_TVEC  57088         // 64
#define FI_SLIST 57152         // 32 int
#define FI_SCNT  57184         // 4
#define SMEM_BYTES 228752

static __device__ __forceinline__ u32 smem_u32(const void* p)
{
    u32 a;
    asm("{ .reg .u64 t; cvta.to.shared.u64 t, %1; cvt.u32.u64 %0, t; }" : "=r"(a) : "l"(p));
    return a;
}
static __device__ __forceinline__ void ldm_x4(u32& r0, u32& r1, u32& r2, u32& r3, u32 addr)
{
    asm volatile("ldmatrix.sync.aligned.m8n8.x4.shared.b16 {%0,%1,%2,%3}, [%4];"
                 : "=r"(r0), "=r"(r1), "=r"(r2), "=r"(r3) : "r"(addr));
}
static __device__ __forceinline__ void ldm_x2(u32& r0, u32& r1, u32 addr)
{
    asm volatile("ldmatrix.sync.aligned.m8n8.x2.shared.b16 {%0,%1}, [%2];"
                 : "=r"(r0), "=r"(r1) : "r"(addr));
}
static __device__ __forceinline__ void ldm_x2t(u32& r0, u32& r1, u32 addr)
{
    asm volatile("ldmatrix.sync.aligned.m8n8.x2.trans.shared.b16 {%0,%1}, [%2];"
                 : "=r"(r0), "=r"(r1) : "r"(addr));
}
static __device__ __forceinline__ void mma_bf16(float* d, u32 a0, u32 a1, u32 a2, u32 a3,
                                                u32 b0, u32 b1)
{
    asm volatile("mma.sync.aligned.m16n8k16.row.col.f32.bf16.bf16.f32 "
                 "{%0,%1,%2,%3}, {%4,%5,%6,%7}, {%8,%9}, {%0,%1,%2,%3};"
                 : "+f"(d[0]), "+f"(d[1]), "+f"(d[2]), "+f"(d[3])
                 : "r"(a0), "r"(a1), "r"(a2), "r"(a3), "r"(b0), "r"(b1));
}
static __device__ __forceinline__ void bsplit(float v, __nv_bfloat16& h, __nv_bfloat16& l)
{
    h = __float2bfloat16_rn(v);
    l = __float2bfloat16_rn(v - __bfloat162float(h));
}
static __device__ __forceinline__ u32 bpack(__nv_bfloat16 a, __nv_bfloat16 b)
{
    return (u32)__bfloat16_as_ushort(a) | ((u32)__bfloat16_as_ushort(b) << 16);
}

// stage one 64-k chunk of W^T (hi/lo, k-pair packed u32) into dst
static __device__ __forceinline__ void stage_chunk(const float* __restrict__ Wg, int ck,
                                                   char* __restrict__ dst, int t, int nth)
{
    for (int u = t; u < 128 * 32; u += nth) {   // f x kpair units
        int kp = u >> 7, f = u & 127;           // consecutive t -> consecutive f (coalesced LDG)
        int k0 = ck * 64 + 2 * kp;
        float v0 = Wg[k0 * HD + f];
        float v1 = Wg[(k0 + 1) * HD + f];
        __nv_bfloat16 h0, l0, h1, l1;
        bsplit(v0, h0, l0);
        bsplit(v1, h1, l1);
        *(u32*)(dst + f * SB2 + kp * 4)         = bpack(h0, h1);
        *(u32*)(dst + WT_LO + f * SB2 + kp * 4) = bpack(l0, l1);
    }
}

__global__ void __launch_bounds__(NT, 1)
sagpool_mma_kernel(const float* __restrict__ x, const int* __restrict__ ei,
                   const float* __restrict__ W1, const float* __restrict__ b1,
                   const float* __restrict__ W2, const float* __restrict__ b2,
                   const float* __restrict__ W3, const float* __restrict__ b3,
                   const float* __restrict__ Wa, const float* __restrict__ ba,
                   const float* __restrict__ M1, const float* __restrict__ c1,
                   const float* __restrict__ M2, const float* __restrict__ c2,
                   const float* __restrict__ M3, const float* __restrict__ c3,
                   float* __restrict__ out)
{
    extern __shared__ float sm[];
    char* smc = (char*)sm;
    float* Af    = sm + FI_AF;
    float* wasf  = sm + FI_WAS;
    float* bsf   = sm + FI_BS;
    float* rd    = sm + FI_RD;
    float* psum  = sm + FI_PSUM;
    float* t1    = sm + FI_T1;
    float* t2    = sm + FI_T2;
    float* sdot  = sm + FI_SDOT;
    float* score = sm + FI_SCORE;
    float* tvec  = sm + FI_TVEC;
    int*   slist = (int*)(sm + FI_SLIST);
    int*   scnt  = (int*)(sm + FI_SCNT);

    const int g    = blockIdx.x;
    const int tid  = threadIdx.x;
    const int wid  = tid >> 5;
    const int lane = tid & 31;
    const int gq   = lane >> 2;
    const int tq   = lane & 3;
    const int base = g * NPG;
    const u32 sbu  = smem_u32(sm);
    const int f0   = (wid & 7) * 16;

    const float* WgL[3] = {W1, W2, W3};
    const float* bgL[3] = {b1, b2, b3};

    // ---- build fp32 adjacency ----
    for (int i = tid; i < NPG * SAF; i += NT) Af[i] = 0.f;
    if (tid == 0) *scnt = 0;
    __syncthreads();
    {
        const int* es = ei + g * EPG;
        const int* ed = ei + ETOT + g * EPG;
        for (int e = tid; e < EPG; e += NT) {
            int s = es[e] - base, d = ed[e] - base;
            Af[s * SAF + d] = 1.f;
            Af[d * SAF + s] = 1.f;
        }
    }
    __syncthreads();
    if (tid < 64) Af[tid * SAF + tid] += 1.f;  // A += I (diag may reach 2)
    __syncthreads();
    {   // rowsum -> dinv (use first 256 threads, 4/row)
        if (tid < 256) {
            int r4 = tid >> 2, l4 = tid & 3;
            float s = 0.f;
            for (int k = l4; k < 64; k += 4) s += Af[r4 * SAF + k];
            s += __shfl_xor_sync(0xFFFFFFFFu, s, 1);
            s += __shfl_xor_sync(0xFFFFFFFFu, s, 2);
            if (l4 == 0) tvec[r4] = rsqrtf(s);
        }
    }
    __syncthreads();
    for (int i = tid; i < NPG * NPG; i += NT) {
        int r = i >> 6, c = i & 63;
        Af[r * SAF + c] *= tvec[r] * tvec[c];   // symmetric
    }
    if (tid < FD) wasf[tid] = Wa[tid];
    bsf[tid] = bgL[tid >> 7][tid & 127];
    __syncthreads();
    // A_adj bf16 hi/lo
    for (int idx = tid; idx < 64 * 64; idx += NT) {
        int m = idx >> 6, j = idx & 63;
        __nv_bfloat16 h, l;
        bsplit(Af[m * SAF + j], h, l);
        *(__nv_bfloat16*)(smc + OFF_ABF + m * SB2 + j * 2)          = h;
        *(__nv_bfloat16*)(smc + OFF_ABF + ABF_LO + m * SB2 + j * 2) = l;
    }
    // x -> xT[k][m] bf16 hi/lo into FT2
    for (int idx = tid; idx < 64 * 32; idx += NT) {
        int m = idx >> 5, kq = idx & 31;
        float4 v = *(const float4*)(x + (base + m) * HD + 4 * kq);
        float va[4] = {v.x, v.y, v.z, v.w};
#pragma unroll
        for (int e = 0; e < 4; ++e) {
            __nv_bfloat16 h, l;
            bsplit(va[e], h, l);
            int k = 4 * kq + e;
            *(__nv_bfloat16*)(smc + OFF_FT2 + k * SB2 + m * 2)         = h;
            *(__nv_bfloat16*)(smc + OFF_FT2 + FT_LO + k * SB2 + m * 2) = l;
        }
    }
    // W1 chunk 0 into buf0 (all threads)
    stage_chunk(W1, 0, smc + OFF_WT0, tid, NT);
    __syncthreads();

    const int inOff[3]  = {OFF_FT2, OFF_FT0, OFF_FT1};
    const int outOff[3] = {OFF_FT0, OFF_FT1, OFF_FT2};
    const u32 wtBuf[2]  = {sbu + OFF_WT0, sbu + OFF_WT1};
    const u32 abfH = sbu + OFF_ABF;

    float dA[8][4];

#pragma unroll 1
    for (int L = 0; L < 3; ++L) {
        const u32 inH  = sbu + inOff[L];
        const int outB = outOff[L];

#pragma unroll 1
        for (int ck = 0; ck < 2; ++ck) {
            const int c = 2 * L + ck;          // global chunk phase
            if (wid < 8) {
                if (ck == 0) {
#pragma unroll
                    for (int j = 0; j < 8; ++j)
#pragma unroll
                        for (int q = 0; q < 4; ++q) dA[j][q] = 0.f;
                }
                const u32 wtH = wtBuf[c & 1];
                // GEMM1 partial: tmpT += W^T chunk @ In^T
#pragma unroll
                for (int s = 0; s < 4; ++s) {
                    u32 aadr = wtH + (u32)((f0 + (lane & 15)) * SB2 + (s * 16 + (lane >> 4) * 8) * 2);
                    u32 ah0, ah1, ah2, ah3, al0, al1, al2, al3;
                    ldm_x4(ah0, ah1, ah2, ah3, aadr);
                    ldm_x4(al0, al1, al2, al3, aadr + WT_LO);
                    int kg = ck * 64 + s * 16;
                    u32 badr = inH + (u32)((kg + (lane & 15)) * SB2);
#pragma unroll
                    for (int j = 0; j < 8; ++j) {
                        u32 bh0, bh1, bl0, bl1;
                        ldm_x2t(bh0, bh1, badr + j * 16);
                        ldm_x2t(bl0, bl1, badr + FT_LO + j * 16);
                        mma_bf16(dA[j], ah0, ah1, ah2, ah3, bh0, bh1);
                        mma_bf16(dA[j], ah0, ah1, ah2, ah3, bl0, bl1);
                        mma_bf16(dA[j], al0, al1, al2, al3, bh0, bh1);
                    }
                }
                if (ck == 1) {
                    // in-register bf16 split of tmpT -> GEMM2 A fragments
                    u32 a2h[4][4], a2l[4][4];
#pragma unroll
                    for (int s = 0; s < 4; ++s)
#pragma unroll
                        for (int q = 0; q < 2; ++q) {
                            __nv_bfloat16 h0, l0, h1, l1;
                            bsplit(dA[2 * s][2 * q], h0, l0);
                            bsplit(dA[2 * s][2 * q + 1], h1, l1);
                            a2h[s][q] = bpack(h0, h1);
                            a2l[s][q] = bpack(l0, l1);
                            bsplit(dA[2 * s + 1][2 * q], h0, l0);
                            bsplit(dA[2 * s + 1][2 * q + 1], h1, l1);
                            a2h[s][2 + q] = bpack(h0, h1);
                            a2l[s][2 + q] = bpack(l0, l1);
                        }
                    // GEMM2: hT = tmpT @ A_adj (symmetric), k=64
                    float dB[8][4];
#pragma unroll
                    for (int n = 0; n < 8; ++n)
#pragma unroll
                        for (int q = 0; q < 4; ++q) dB[n][q] = 0.f;
#pragma unroll
                    for (int s = 0; s < 4; ++s)
#pragma unroll
                        for (int n = 0; n < 8; ++n) {
                            u32 ba = abfH + (u32)((n * 8 + (lane & 7)) * SB2 +
                                                  (s * 16 + ((lane >> 3) & 1) * 8) * 2);
                            u32 bh0, bh1, bl0, bl1;
                            ldm_x2(bh0, bh1, ba);
                            ldm_x2(bl0, bl1, ba + ABF_LO);
                            mma_bf16(dB[n], a2h[s][0], a2h[s][1], a2h[s][2], a2h[s][3], bh0, bh1);
                            mma_bf16(dB[n], a2h[s][0], a2h[s][1], a2h[s][2], a2h[s][3], bl0, bl1);
                            mma_bf16(dB[n], a2l[s][0], a2l[s][1], a2l[s][2], a2l[s][3], bh0, bh1);
                        }
                    // epilogue: h = relu(D2 + b); store hT hi/lo
                    float b0v = bsf[L * 128 + f0 + gq], b1v = bsf[L * 128 + f0 + 8 + gq];
#pragma unroll
                    for (int n = 0; n < 8; ++n) {
                        int m0 = n * 8 + 2 * tq;
                        float v00 = fmaxf(dB[n][0] + b0v, 0.f);
                        float v01 = fmaxf(dB[n][1] + b0v, 0.f);
                        float v10 = fmaxf(dB[n][2] + b1v, 0.f);
                        float v11 = fmaxf(dB[n][3] + b1v, 0.f);
                        __nv_bfloat16 h0, l0, h1, l1;
                        bsplit(v00, h0, l0); bsplit(v01, h1, l1);
                        *(u32*)(smc + outB + (f0 + gq) * SB2 + m0 * 2)         = bpack(h0, h1);
                        *(u32*)(smc + outB + FT_LO + (f0 + gq) * SB2 + m0 * 2) = bpack(l0, l1);
                        bsplit(v10, h0, l0); bsplit(v11, h1, l1);
                        *(u32*)(smc + outB + (f0 + 8 + gq) * SB2 + m0 * 2)         = bpack(h0, h1);
                        *(u32*)(smc + outB + FT_LO + (f0 + 8 + gq) * SB2 + m0 * 2) = bpack(l0, l1);
                    }
                }
            } else {
                // stager warps: prepare chunk c+1 into the other buffer
                int nc = c + 1;
                if (nc < 6)
                    stage_chunk(WgL[nc >> 1], nc & 1,
                                smc + ((nc & 1) ? OFF_WT1 : OFF_WT0), tid - 256, 128);
            }
            __syncthreads();
        }
    }

    const int ftOff[3] = {OFF_FT0, OFF_FT1, OFF_FT2};
    // ---- sdot[m] = sum_f feats[m][f]*Wa[f]  (4 threads per m) ----
    if (tid < 256) {
        int m = tid >> 2, l4 = tid & 3;
        float s = 0.f;
#pragma unroll
        for (int lay = 0; lay < 3; ++lay) {
            const char* bh = smc + ftOff[lay];
            for (int f = l4; f < HD; f += 4) {
                float v = __bfloat162float(*(const __nv_bfloat16*)(bh + f * SB2 + m * 2))
                        + __bfloat162float(*(const __nv_bfloat16*)(bh + FT_LO + f * SB2 + m * 2));
                s = fmaf(v, wasf[lay * HD + f], s);
            }
        }
        s += __shfl_xor_sync(0xFFFFFFFFu, s, 1);
        s += __shfl_xor_sync(0xFFFFFFFFu, s, 2);
        if (l4 == 0) sdot[m] = s;
    }
    __syncthreads();
    // ---- score = tanh(A @ sdot + ba) ----
    if (tid < 64) {
        float s = 0.f;
        for (int k = 0; k < 64; ++k) s = fmaf(Af[tid * SAF + k], sdot[k], s);
        score[tid] = tanhf(s + ba[0]);
    }
    __syncthreads();
    // ---- top-K (jax tie-break: smaller index wins among equals) ----
    if (tid < 64) {
        float si = score[tid];
        int rank = 0;
#pragma unroll
        for (int j = 0; j < 64; ++j) {
            float sj = score[j];
            rank += (sj > si) || (sj == si && j < tid);
        }
        if (rank < KSEL) { int p = atomicAdd(scnt, 1); slist[p] = tid; }
    }
    __syncthreads();
    // ---- readout: mean || max of feats*score over selected ----
    for (int c = tid; c < FD; c += NT) {
        const char* bh = smc + ftOff[c >> 7] + (c & 127) * SB2;
        float ssum = 0.f, mx = -FLT_MAX;
#pragma unroll
        for (int j = 0; j < KSEL; ++j) {
            int m = slist[j];
            float v = __bfloat162float(*(const __nv_bfloat16*)(bh + m * 2))
                    + __bfloat162float(*(const __nv_bfloat16*)(bh + FT_LO + m * 2));
            v *= score[m];
            ssum += v;
            mx = fmaxf(mx, v);
        }
        rd[c]      = ssum * (1.f / (float)KSEL);
        rd[FD + c] = mx;
    }
    __syncthreads();
    // ---- MLP1: [768]->[128], 3 partials ----
    {
        int j = tid & 127, q = tid >> 7;  // q 0..2
        float a = 0.f;
        for (int c = q * 256; c < q * 256 + 256; ++c)
            a = fmaf(rd[c], M1[c * HD + j], a);
        psum[tid] = a;
        __syncthreads();
        if (tid < 128) t1[tid] = fmaxf(psum[tid] + psum[tid + 128] + psum[tid + 256] + c1[tid], 0.f);
    }
    __syncthreads();
    // ---- MLP2: [128]->[64], 4 partials (first 256 threads) ----
    {
        if (tid < 256) {
            int j = tid & 63, q = tid >> 6;
            float a = 0.f;
#pragma unroll
            for (int c = q * 32; c < q * 32 + 32; ++c)
                a = fmaf(t1[c], M2[c * 64 + j], a);
            psum[tid] = a;
        }
        __syncthreads();
        if (tid < 64)
            t2[tid] = fmaxf(psum[tid] + psum[tid + 64] + psum[tid + 128] + psum[tid + 192] + c2[tid], 0.f);
    }
    __syncthreads();
    // ---- MLP3: [64]->[10] ----
    if (tid < DOUT) {
        float a = c3[tid];
#pragma unroll
        for (int c = 0; c < 64; ++c) a = fmaf(t2[c], M3[c * DOUT + tid], a);
        out[g * DOUT + tid] = a;
    }
}

extern "C" void kernel_launch(void* const* d_in, const int* in_sizes, int n_in,
                              void* d_out, int out_size)
{
    const float* x  = (const float*)d_in[0];
    const int*   ei = (const int*)d_in[1];
    // d_in[2] = batch (unused: graphs are contiguous 64-node blocks)
    const float* W1 = (const float*)d_in[3];
    const float* b1 = (const float*)d_in[4];
    const float* W2 = (const float*)d_in[5];
    const float* b2 = (const float*)d_in[6];
    const float* W3 = (const float*)d_in[7];
    const float* b3 = (const float*)d_in[8];
    const float* Wa = (const float*)d_in[9];
    const float* ba = (const float*)d_in[10];
    const float* M1 = (const float*)d_in[11];
    const float* c1 = (const float*)d_in[12];
    const float* M2 = (const float*)d_in[13];
    const float* c2 = (const float*)d_in[14];
    const float* M3 = (const float*)d_in[15];
    const float* c3 = (const float*)d_in[16];
    float* out = (float*)d_out;

    cudaFuncSetAttribute(sagpool_mma_kernel,
                         cudaFuncAttributeMaxDynamicSharedMemorySize, SMEM_BYTES);
    sagpool_mma_kernel<<<NG, NT, SMEM_BYTES>>>(x, ei, W1, b1, W2, b2, W3, b3,
                                               Wa, ba, M1, c1, M2, c2, M3, c3, out);
}

// round 14
// speedup vs baseline: 1.5369x; 1.5369x over previous
#include <cuda_runtime.h>
#include <cuda_bf16.h>
#include <stdint.h>
#include <float.h>

// Problem constants
#define NG    128
#define NPG   64
#define EPG   1024
#define ETOT  131072
#define HD    128
#define FD    384
#define KSEL  32
#define DOUT  10
#define NT    256      // 8 warps

typedef uint32_t u32;

// ---- smem byte layout (bf16 buffers, row stride 144B) ----
#define SB2     144
#define FT_LO   18432          // lo half within a buffer (128 rows x 144B)
#define OFF_FT0 0              // h1 hi+lo  36864B
#define OFF_FT1 36864          // h2
#define OFF_FT2 73728          // x then h3
#define OFF_ABF 110592         // A_adj bf16 hi (64x144); lo +9216
#define ABF_LO  9216
#define OFF_WT0 129024         // W^T chunk buf0 (hi 18432 + lo 18432)
#define OFF_WT1 165888         // W^T chunk buf1
#define WT_LO   18432
// fp32 region (float indices into sm[])
#define FI_AF    50688         // 64 x 65
#define SAF      65
#define FI_WAS   54848         // 384
#define FI_BS    55232         // 384 (all 3 layer biases)
#define FI_RD    55616         // 768
#define FI_PSUM  56384         // 256
#define FI_T1    56768         // 128
#define FI_T2    56896         // 64
#define FI_SDOT  56960         // 64
#define FI_SCORE 57024         // 64
#define FI_TVEC  57088         // 64
#define FI_SLIST 57152         // 32 int
#define FI_SCNT  57184         // 4
#define SMEM_BYTES 228752

// ---- pre-converted operand storage (written by prep kernel) ----
// g_wt: 6 chunks x (hi 4096 u32 + lo 4096 u32); chunk layout [f:128][kp:32]
__device__ u32 g_wt[6 * 8192];
// g_xt: per graph (hi 4096 + lo 4096); layout [k:128][mp:32]
__device__ u32 g_xt[NG * 8192];

static __device__ __forceinline__ u32 smem_u32(const void* p)
{
    u32 a;
    asm("{ .reg .u64 t; cvta.to.shared.u64 t, %1; cvt.u32.u64 %0, t; }" : "=r"(a) : "l"(p));
    return a;
}
static __device__ __forceinline__ void cpa16(u32 dst, const void* src)
{
    asm volatile("cp.async.cg.shared.global [%0], [%1], 16;" :: "r"(dst), "l"(src) : "memory");
}
#define CPA_COMMIT() asm volatile("cp.async.commit_group;" ::: "memory")
#define CPA_WAIT(n)  asm volatile("cp.async.wait_group %0;" :: "n"(n) : "memory")

static __device__ __forceinline__ void ldm_x4(u32& r0, u32& r1, u32& r2, u32& r3, u32 addr)
{
    asm volatile("ldmatrix.sync.aligned.m8n8.x4.shared.b16 {%0,%1,%2,%3}, [%4];"
                 : "=r"(r0), "=r"(r1), "=r"(r2), "=r"(r3) : "r"(addr));
}
static __device__ __forceinline__ void ldm_x2(u32& r0, u32& r1, u32 addr)
{
    asm volatile("ldmatrix.sync.aligned.m8n8.x2.shared.b16 {%0,%1}, [%2];"
                 : "=r"(r0), "=r"(r1) : "r"(addr));
}
static __device__ __forceinline__ void ldm_x2t(u32& r0, u32& r1, u32 addr)
{
    asm volatile("ldmatrix.sync.aligned.m8n8.x2.trans.shared.b16 {%0,%1}, [%2];"
                 : "=r"(r0), "=r"(r1) : "r"(addr));
}
static __device__ __forceinline__ void mma_bf16(float* d, u32 a0, u32 a1, u32 a2, u32 a3,
                                                u32 b0, u32 b1)
{
    asm volatile("mma.sync.aligned.m16n8k16.row.col.f32.bf16.bf16.f32 "
                 "{%0,%1,%2,%3}, {%4,%5,%6,%7}, {%8,%9}, {%0,%1,%2,%3};"
                 : "+f"(d[0]), "+f"(d[1]), "+f"(d[2]), "+f"(d[3])
                 : "r"(a0), "r"(a1), "r"(a2), "r"(a3), "r"(b0), "r"(b1));
}
static __device__ __forceinline__ void bsplit(float v, __nv_bfloat16& h, __nv_bfloat16& l)
{
    h = __float2bfloat16_rn(v);
    l = __float2bfloat16_rn(v - __bfloat162float(h));
}
static __device__ __forceinline__ u32 bpack(__nv_bfloat16 a, __nv_bfloat16 b)
{
    return (u32)__bfloat16_as_ushort(a) | ((u32)__bfloat16_as_ushort(b) << 16);
}

// copy one 36864B hi/lo buffer (2048 16B units) global->shared via cp.async
static __device__ __forceinline__ void copy_buf_async(const u32* __restrict__ src_base,
                                                      u32 dstb, int t)
{
#pragma unroll
    for (int i = 0; i < 8; ++i) {
        int u = t + i * NT;
        int half = u >> 10, v = u & 1023;
        int f = v >> 3, seg = v & 7;
        cpa16(dstb + half * WT_LO + f * SB2 + seg * 16,
              src_base + half * 4096 + f * 32 + seg * 4);
    }
}

// ============================================================================
// Prep kernel: blocks 0..127 transpose+split x per graph; blocks 128..133 split W
// ============================================================================
__global__ void __launch_bounds__(256, 1)
prep_kernel(const float* __restrict__ x,
            const float* __restrict__ W1, const float* __restrict__ W2,
            const float* __restrict__ W3)
{
    const int b = blockIdx.x, t = threadIdx.x;
    if (b < NG) {
        __shared__ float xs[64 * 130];
        const float4* xg = (const float4*)(x + b * NPG * HD);
        for (int i = t; i < 2048; i += 256) {
            float4 v = xg[i];
            int m = i >> 5, kq = i & 31;
            float* d = xs + m * 130 + 4 * kq;
            d[0] = v.x; d[1] = v.y; d[2] = v.z; d[3] = v.w;
        }
        __syncthreads();
        u32* dstg = g_xt + b * 8192;
        for (int i = t; i < 4096; i += 256) {
            int k = i >> 5, mp = i & 31;
            __nv_bfloat16 h0, l0, h1, l1;
            bsplit(xs[(2 * mp) * 130 + k], h0, l0);
            bsplit(xs[(2 * mp + 1) * 130 + k], h1, l1);
            dstg[k * 32 + mp]        = bpack(h0, h1);
            dstg[4096 + k * 32 + mp] = bpack(l0, l1);
        }
    } else {
        int c = b - NG;                       // chunk 0..5
        const float* Wg = (c < 2) ? W1 : (c < 4) ? W2 : W3;
        int ck = c & 1;
        u32* dstg = g_wt + c * 8192;
        for (int i = t; i < 4096; i += 256) {
            int kp = i >> 7, f = i & 127;     // coalesced LDG over f
            __nv_bfloat16 h0, l0, h1, l1;
            bsplit(Wg[(ck * 64 + 2 * kp) * HD + f], h0, l0);
            bsplit(Wg[(ck * 64 + 2 * kp + 1) * HD + f], h1, l1);
            dstg[f * 32 + kp]        = bpack(h0, h1);
            dstg[4096 + f * 32 + kp] = bpack(l0, l1);
        }
    }
}

// ============================================================================
// Main kernel
// ============================================================================
__global__ void __launch_bounds__(NT, 1)
sagpool_mma_kernel(const float* __restrict__ x, const int* __restrict__ ei,
                   const float* __restrict__ b1, const float* __restrict__ b2,
                   const float* __restrict__ b3,
                   const float* __restrict__ Wa, const float* __restrict__ ba,
                   const float* __restrict__ M1, const float* __restrict__ c1,
                   const float* __restrict__ M2, const float* __restrict__ c2,
                   const float* __restrict__ M3, const float* __restrict__ c3,
                   float* __restrict__ out)
{
    extern __shared__ float sm[];
    char* smc = (char*)sm;
    float* Af    = sm + FI_AF;
    float* wasf  = sm + FI_WAS;
    float* bsf   = sm + FI_BS;
    float* rd    = sm + FI_RD;
    float* psum  = sm + FI_PSUM;
    float* t1    = sm + FI_T1;
    float* t2    = sm + FI_T2;
    float* sdot  = sm + FI_SDOT;
    float* score = sm + FI_SCORE;
    float* tvec  = sm + FI_TVEC;
    int*   slist = (int*)(sm + FI_SLIST);
    int*   scnt  = (int*)(sm + FI_SCNT);

    const int g    = blockIdx.x;
    const int tid  = threadIdx.x;
    const int wid  = tid >> 5;
    const int lane = tid & 31;
    const int gq   = lane >> 2;
    const int tq   = lane & 3;
    const int base = g * NPG;
    const u32 sbu  = smem_u32(sm);
    const int f0   = wid * 16;

    // ---- kick off async copies: x -> FT2, W chunk0 -> WT0 (overlap with A build) ----
    copy_buf_async(g_xt + g * 8192, sbu + OFF_FT2, tid);
    copy_buf_async(g_wt,            sbu + OFF_WT0, tid);
    CPA_COMMIT();   // group: {x, W0}

    // ---- build fp32 adjacency ----
    for (int i = tid; i < NPG * SAF; i += NT) Af[i] = 0.f;
    if (tid == 0) *scnt = 0;
    __syncthreads();
    {
        const int* es = ei + g * EPG;
        const int* ed = ei + ETOT + g * EPG;
        for (int e = tid; e < EPG; e += NT) {
            int s = es[e] - base, d = ed[e] - base;
            Af[s * SAF + d] = 1.f;
            Af[d * SAF + s] = 1.f;
        }
    }
    __syncthreads();
    if (tid < 64) Af[tid * SAF + tid] += 1.f;  // A += I (diag may reach 2)
    __syncthreads();
    {   // rowsum -> dinv (4 threads/row)
        int r4 = tid >> 2, l4 = tid & 3;
        float s = 0.f;
        for (int k = l4; k < 64; k += 4) s += Af[r4 * SAF + k];
        s += __shfl_xor_sync(0xFFFFFFFFu, s, 1);
        s += __shfl_xor_sync(0xFFFFFFFFu, s, 2);
        if (l4 == 0) tvec[r4] = rsqrtf(s);
    }
    __syncthreads();
    for (int i = tid; i < NPG * NPG; i += NT) {
        int r = i >> 6, c = i & 63;
        Af[r * SAF + c] *= tvec[r] * tvec[c];   // symmetric
    }
    // small params
    if (tid < FD) { wasf[tid] = Wa[tid]; if (tid + NT < FD) wasf[tid + NT] = Wa[tid + NT]; }
    bsf[tid] = (tid < 128) ? b1[tid] : b2[tid - 128];
    if (tid < 128) bsf[256 + tid] = b3[tid];
    __syncthreads();
    // A_adj bf16 hi/lo (u32-packed stores)
    for (int idx = tid; idx < 64 * 32; idx += NT) {
        int m = idx >> 5, jp = idx & 31;
        __nv_bfloat16 h0, l0, h1, l1;
        bsplit(Af[m * SAF + 2 * jp], h0, l0);
        bsplit(Af[m * SAF + 2 * jp + 1], h1, l1);
        *(u32*)(smc + OFF_ABF + m * SB2 + jp * 4)          = bpack(h0, h1);
        *(u32*)(smc + OFF_ABF + ABF_LO + m * SB2 + jp * 4) = bpack(l0, l1);
    }
    __syncthreads();

    const int inOff[3]  = {OFF_FT2, OFF_FT0, OFF_FT1};
    const int outOff[3] = {OFF_FT0, OFF_FT1, OFF_FT2};
    const u32 wtBuf[2]  = {sbu + OFF_WT0, sbu + OFF_WT1};
    const u32 abfH = sbu + OFF_ABF;

    float dA[8][4];

#pragma unroll 1
    for (int L = 0; L < 3; ++L) {
        const u32 inH  = sbu + inOff[L];
        const int outB = outOff[L];

#pragma unroll 1
        for (int ck = 0; ck < 2; ++ck) {
            const int c = 2 * L + ck;
            // prefetch next chunk into the other buffer; wait for current
            if (c < 5) {
                copy_buf_async(g_wt + (c + 1) * 8192, wtBuf[(c + 1) & 1], tid);
                CPA_COMMIT();
                CPA_WAIT(1);
            } else {
                CPA_WAIT(0);
            }
            __syncthreads();

            if (ck == 0) {
#pragma unroll
                for (int j = 0; j < 8; ++j)
#pragma unroll
                    for (int q = 0; q < 4; ++q) dA[j][q] = 0.f;
            }
            const u32 wtH = wtBuf[c & 1];
            // GEMM1 partial: tmpT += W^T chunk @ In^T
#pragma unroll
            for (int s = 0; s < 4; ++s) {
                u32 aadr = wtH + (u32)((f0 + (lane & 15)) * SB2 + (s * 16 + (lane >> 4) * 8) * 2);
                u32 ah0, ah1, ah2, ah3, al0, al1, al2, al3;
                ldm_x4(ah0, ah1, ah2, ah3, aadr);
                ldm_x4(al0, al1, al2, al3, aadr + WT_LO);
                int kg = ck * 64 + s * 16;
                u32 badr = inH + (u32)((kg + (lane & 15)) * SB2);
#pragma unroll
                for (int j = 0; j < 8; ++j) {
                    u32 bh0, bh1, bl0, bl1;
                    ldm_x2t(bh0, bh1, badr + j * 16);
                    ldm_x2t(bl0, bl1, badr + FT_LO + j * 16);
                    mma_bf16(dA[j], ah0, ah1, ah2, ah3, bh0, bh1);
                    mma_bf16(dA[j], ah0, ah1, ah2, ah3, bl0, bl1);
                    mma_bf16(dA[j], al0, al1, al2, al3, bh0, bh1);
                }
            }
            if (ck == 1) {
                // in-register bf16 split of tmpT -> GEMM2 A fragments
                u32 a2h[4][4], a2l[4][4];
#pragma unroll
                for (int s = 0; s < 4; ++s)
#pragma unroll
                    for (int q = 0; q < 2; ++q) {
                        __nv_bfloat16 h0, l0, h1, l1;
                        bsplit(dA[2 * s][2 * q], h0, l0);
                        bsplit(dA[2 * s][2 * q + 1], h1, l1);
                        a2h[s][q] = bpack(h0, h1);
                        a2l[s][q] = bpack(l0, l1);
                        bsplit(dA[2 * s + 1][2 * q], h0, l0);
                        bsplit(dA[2 * s + 1][2 * q + 1], h1, l1);
                        a2h[s][2 + q] = bpack(h0, h1);
                        a2l[s][2 + q] = bpack(l0, l1);
                    }
                // GEMM2: hT = tmpT @ A_adj (symmetric), k=64
                float dB[8][4];
#pragma unroll
                for (int n = 0; n < 8; ++n)
#pragma unroll
                    for (int q = 0; q < 4; ++q) dB[n][q] = 0.f;
#pragma unroll
                for (int s = 0; s < 4; ++s)
#pragma unroll
                    for (int n = 0; n < 8; ++n) {
                        u32 ba = abfH + (u32)((n * 8 + (lane & 7)) * SB2 +
                                              (s * 16 + ((lane >> 3) & 1) * 8) * 2);
                        u32 bh0, bh1, bl0, bl1;
                        ldm_x2(bh0, bh1, ba);
                        ldm_x2(bl0, bl1, ba + ABF_LO);
                        mma_bf16(dB[n], a2h[s][0], a2h[s][1], a2h[s][2], a2h[s][3], bh0, bh1);
                        mma_bf16(dB[n], a2h[s][0], a2h[s][1], a2h[s][2], a2h[s][3], bl0, bl1);
                        mma_bf16(dB[n], a2l[s][0], a2l[s][1], a2l[s][2], a2l[s][3], bh0, bh1);
                    }
                // epilogue: h = relu(D2 + b); store hT hi/lo
                float b0v = bsf[L * 128 + f0 + gq], b1v = bsf[L * 128 + f0 + 8 + gq];
#pragma unroll
                for (int n = 0; n < 8; ++n) {
                    int m0 = n * 8 + 2 * tq;
                    float v00 = fmaxf(dB[n][0] + b0v, 0.f);
                    float v01 = fmaxf(dB[n][1] + b0v, 0.f);
                    float v10 = fmaxf(dB[n][2] + b1v, 0.f);
                    float v11 = fmaxf(dB[n][3] + b1v, 0.f);
                    __nv_bfloat16 h0, l0, h1, l1;
                    bsplit(v00, h0, l0); bsplit(v01, h1, l1);
                    *(u32*)(smc + outB + (f0 + gq) * SB2 + m0 * 2)         = bpack(h0, h1);
                    *(u32*)(smc + outB + FT_LO + (f0 + gq) * SB2 + m0 * 2) = bpack(l0, l1);
                    bsplit(v10, h0, l0); bsplit(v11, h1, l1);
                    *(u32*)(smc + outB + (f0 + 8 + gq) * SB2 + m0 * 2)         = bpack(h0, h1);
                    *(u32*)(smc + outB + FT_LO + (f0 + 8 + gq) * SB2 + m0 * 2) = bpack(l0, l1);
                }
            }
            __syncthreads();
        }
    }

    const int ftOff[3] = {OFF_FT0, OFF_FT1, OFF_FT2};
    // ---- sdot[m] = sum_f feats[m][f]*Wa[f]  (4 threads per m) ----
    {
        int m = tid >> 2, l4 = tid & 3;
        float s = 0.f;
#pragma unroll
        for (int lay = 0; lay < 3; ++lay) {
            const char* bh = smc + ftOff[lay];
            for (int f = l4; f < HD; f += 4) {
                float v = __bfloat162float(*(const __nv_bfloat16*)(bh + f * SB2 + m * 2))
                        + __bfloat162float(*(const __nv_bfloat16*)(bh + FT_LO + f * SB2 + m * 2));
                s = fmaf(v, wasf[lay * HD + f], s);
            }
        }
        s += __shfl_xor_sync(0xFFFFFFFFu, s, 1);
        s += __shfl_xor_sync(0xFFFFFFFFu, s, 2);
        if (l4 == 0) sdot[m] = s;
    }
    __syncthreads();
    // ---- score = tanh(A @ sdot + ba) ----
    if (tid < 64) {
        float s = 0.f;
        for (int k = 0; k < 64; ++k) s = fmaf(Af[tid * SAF + k], sdot[k], s);
        score[tid] = tanhf(s + ba[0]);
    }
    __syncthreads();
    // ---- top-K (jax tie-break: smaller index wins among equals) ----
    if (tid < 64) {
        float si = score[tid];
        int rank = 0;
#pragma unroll
        for (int j = 0; j < 64; ++j) {
            float sj = score[j];
            rank += (sj > si) || (sj == si && j < tid);
        }
        if (rank < KSEL) { int p = atomicAdd(scnt, 1); slist[p] = tid; }
    }
    __syncthreads();
    // ---- readout: mean || max of feats*score over selected ----
    for (int c = tid; c < FD; c += NT) {
        const char* bh = smc + ftOff[c >> 7] + (c & 127) * SB2;
        float ssum = 0.f, mx = -FLT_MAX;
#pragma unroll
        for (int j = 0; j < KSEL; ++j) {
            int m = slist[j];
            float v = __bfloat162float(*(const __nv_bfloat16*)(bh + m * 2))
                    + __bfloat162float(*(const __nv_bfloat16*)(bh + FT_LO + m * 2));
            v *= score[m];
            ssum += v;
            mx = fmaxf(mx, v);
        }
        rd[c]      = ssum * (1.f / (float)KSEL);
        rd[FD + c] = mx;
    }
    __syncthreads();
    // ---- MLP1: [768]->[128], 2 partials ----
    {
        int j = tid & 127, q = tid >> 7;
        float a = 0.f;
        for (int c = q * 384; c < q * 384 + 384; ++c)
            a = fmaf(rd[c], M1[c * HD + j], a);
        psum[tid] = a;
        __syncthreads();
        if (tid < 128) t1[tid] = fmaxf(psum[tid] + psum[tid + 128] + c1[tid], 0.f);
    }
    __syncthreads();
    // ---- MLP2: [128]->[64], 4 partials ----
    {
        int j = tid & 63, q = tid >> 6;
        float a = 0.f;
#pragma unroll
        for (int c = q * 32; c < q * 32 + 32; ++c)
            a = fmaf(t1[c], M2[c * 64 + j], a);
        psum[tid] = a;
        __syncthreads();
        if (tid < 64)
            t2[tid] = fmaxf(psum[tid] + psum[tid + 64] + psum[tid + 128] + psum[tid + 192] + c2[tid], 0.f);
    }
    __syncthreads();
    // ---- MLP3: [64]->[10] ----
    if (tid < DOUT) {
        float a = c3[tid];
#pragma unroll
        for (int c = 0; c < 64; ++c) a = fmaf(t2[c], M3[c * DOUT + tid], a);
        out[g * DOUT + tid] = a;
    }
}

extern "C" void kernel_launch(void* const* d_in, const int* in_sizes, int n_in,
                              void* d_out, int out_size)
{
    const float* x  = (const float*)d_in[0];
    const int*   ei = (const int*)d_in[1];
    // d_in[2] = batch (unused: graphs are contiguous 64-node blocks)
    const float* W1 = (const float*)d_in[3];
    const float* b1 = (const float*)d_in[4];
    const float* W2 = (const float*)d_in[5];
    const float* b2 = (const float*)d_in[6];
    const float* W3 = (const float*)d_in[7];
    const float* b3 = (const float*)d_in[8];
    const float* Wa = (const float*)d_in[9];
    const float* ba = (const float*)d_in[10];
    const float* M1 = (const float*)d_in[11];
    const float* c1 = (const float*)d_in[12];
    const float* M2 = (const float*)d_in[13];
    const float* c2 = (const float*)d_in[14];
    const float* M3 = (const float*)d_in[15];
    const float* c3 = (const float*)d_in[16];
    float* out = (float*)d_out;

    prep_kernel<<<NG + 6, 256>>>(x, W1, W2, W3);

    cudaFuncSetAttribute(sagpool_mma_kernel,
                         cudaFuncAttributeMaxDynamicSharedMemorySize, SMEM_BYTES);
    sagpool_mma_kernel<<<NG, NT, SMEM_BYTES>>>(x, ei, b1, b2, b3,
                                               Wa, ba, M1, c1, M2, c2, M3, c3, out);
}